// round 15
// baseline (speedup 1.0000x reference)
#include <cuda_runtime.h>
#include <cuda_fp16.h>
#include <cstdint>
#include <math.h>

#define H      1024
#define INNER  2048
#define NST    16
#define DTR    64
#define BATCH  2
#define SEQ    1024
#define TOK    (BATCH*SEQ)   // 2048

// ======================= PTX helpers (plain sm_103 legal) ====================
__device__ __forceinline__ uint32_t smem_u32(const void* p) {
    uint32_t a;
    asm("{ .reg .u64 t; cvta.to.shared.u64 t, %1; cvt.u32.u64 %0, t; }"
        : "=r"(a) : "l"(p));
    return a;
}
__device__ __forceinline__ void cp16(uint32_t saddr, const void* g) {
    asm volatile("cp.async.cg.shared.global [%0], [%1], 16;"
                 :: "r"(saddr), "l"(g) : "memory");
}
#define CP_COMMIT() asm volatile("cp.async.commit_group;" ::: "memory")
#define CP_WAIT1()  asm volatile("cp.async.wait_group 1;" ::: "memory")

__device__ __forceinline__ void ldsm_x4(uint32_t* r, uint32_t addr) {
    asm volatile("ldmatrix.sync.aligned.m8n8.x4.shared.b16 {%0,%1,%2,%3}, [%4];"
                 : "=r"(r[0]), "=r"(r[1]), "=r"(r[2]), "=r"(r[3]) : "r"(addr));
}
__device__ __forceinline__ void mma_f16(float* c, const uint32_t* a, const uint32_t* b) {
    asm volatile("mma.sync.aligned.m16n8k16.row.col.f32.f16.f16.f32 "
                 "{%0,%1,%2,%3}, {%4,%5,%6,%7}, {%8,%9}, {%0,%1,%2,%3};"
                 : "+f"(c[0]), "+f"(c[1]), "+f"(c[2]), "+f"(c[3])
                 : "r"(a[0]), "r"(a[1]), "r"(a[2]), "r"(a[3]),
                   "r"(b[0]), "r"(b[1]));
}

// ======================= scratch buffers ====================================
__device__ __align__(16) __half gA_in [TOK * H];
__device__ __align__(16) __half gB_in [2 * INNER * H];
__device__ __align__(16) float  g_xz  [TOK * 2 * INNER];
__device__ __align__(16) float  g_xa  [TOK * INNER];
__device__ __align__(16) float  g_bcdtr[TOK * 96];
__device__ __align__(16) __half gA_dtr[TOK * DTR];
__device__ __align__(16) __half gB_dt [INNER * DTR];
__device__ __align__(16) float  g_dt  [TOK * INNER];
__device__ __align__(16) float  g_dtpart[16 * TOK];
__device__                float g_dtmean[TOK];
__device__ __align__(16) __half gA_out[TOK * INNER];
__device__ __align__(16) __half gB_out[H * INNER];

#define LDSTR 72

// ======================= 128x128 warp-MMA GEMM (3-stage) =====================
// EPI = 0: plain; EPI = 1: softplus+clip + per-CTA row-sum partials (dt path).
#define BM    128
#define BN    128
#define BKE   64
#define BUFE  ((BM + BN) * LDSTR)
#define STGB  (BUFE * 2)             // 36864 B
#define NSTG  3

template <int EPI>
__global__ void __launch_bounds__(256, 2)
gemm_h(const __half* __restrict__ A, const __half* __restrict__ B,
       const float* __restrict__ bias, float* __restrict__ C,
       float* __restrict__ part,
       int K, int ldc, int nvalid) {
    extern __shared__ __align__(16) __half sm[];
    const uint32_t smb = smem_u32(sm);

    const int tid = threadIdx.x;
    const int lane = tid & 31, wid = tid >> 5;
    const int m0 = blockIdx.y * BM, n0 = blockIdx.x * BN;
    const int wm = (wid & 3) * 32;
    const int wn = (wid >> 2) * 64;

    float acc[2][8][4];
    #pragma unroll
    for (int i = 0; i < 2; i++)
        #pragma unroll
        for (int j = 0; j < 8; j++)
            #pragma unroll
            for (int k = 0; k < 4; k++) acc[i][j][k] = 0.f;

    const int nc = K >> 6;

    auto load_tile = [&](int stg, int kc) {
        const __half* Ag = A + (size_t)m0 * K + kc * BKE;
        const __half* Bg = B + (size_t)n0 * K + kc * BKE;
        uint32_t sa = smb + stg * STGB;
        uint32_t sbb = sa + BM * LDSTR * 2;
        #pragma unroll
        for (int i = 0; i < 4; i++) {
            int ci = tid + i * 256;
            int row = ci >> 3, c8 = ci & 7;
            uint32_t so = (uint32_t)(row * LDSTR + c8 * 8) * 2;
            cp16(sa + so,  Ag + (size_t)row * K + c8 * 8);
            cp16(sbb + so, Bg + (size_t)row * K + c8 * 8);
        }
    };

    load_tile(0, 0);
    CP_COMMIT();
    if (nc > 1) load_tile(1, 1);
    CP_COMMIT();

    int cs = 0, ls = 2;
    for (int c = 0; c < nc; c++) {
        CP_WAIT1();
        __syncthreads();
        if (c + 2 < nc) {
            load_tile(ls, c + 2);
            ls = (ls + 1 == NSTG) ? 0 : ls + 1;
        }
        CP_COMMIT();

        const uint32_t a_base = smb + cs * STGB;
        const uint32_t b_base = a_base + BM * LDSTR * 2;

        #pragma unroll
        for (int kk = 0; kk < 4; kk++) {
            uint32_t afr[2][4];
            #pragma unroll
            for (int mt = 0; mt < 2; mt++) {
                int row = wm + mt * 16 + (lane & 15);
                int col = kk * 16 + (lane >> 4) * 8;
                ldsm_x4(afr[mt], a_base + (uint32_t)(row * LDSTR + col) * 2);
            }
            uint32_t bfr[8][2];
            #pragma unroll
            for (int p = 0; p < 4; p++) {
                int g = lane >> 3, idx = lane & 7;
                int row = wn + p * 16 + idx + (g >> 1) * 8;
                int col = kk * 16 + (g & 1) * 8;
                uint32_t r[4];
                ldsm_x4(r, b_base + (uint32_t)(row * LDSTR + col) * 2);
                bfr[2 * p][0] = r[0];     bfr[2 * p][1] = r[1];
                bfr[2 * p + 1][0] = r[2]; bfr[2 * p + 1][1] = r[3];
            }
            #pragma unroll
            for (int mt = 0; mt < 2; mt++)
                #pragma unroll
                for (int nt = 0; nt < 8; nt++)
                    mma_f16(acc[mt][nt], afr[mt], bfr[nt]);
        }
        cs = (cs + 1 == NSTG) ? 0 : cs + 1;
    }

    float rs[2][2] = {{0.f, 0.f}, {0.f, 0.f}};

    #pragma unroll
    for (int mt = 0; mt < 2; mt++) {
        #pragma unroll
        for (int nt = 0; nt < 8; nt++) {
            int row = m0 + wm + mt * 16 + (lane >> 2);
            int col = n0 + wn + nt * 8 + (lane & 3) * 2;
            if (col < nvalid) {
                float b0 = bias[col], b1 = bias[col + 1];
                float v00 = acc[mt][nt][0] + b0, v01 = acc[mt][nt][1] + b1;
                float v10 = acc[mt][nt][2] + b0, v11 = acc[mt][nt][3] + b1;
                if (EPI == 1) {
                    v00 = (v00 > 20.f) ? v00 : log1pf(__expf(v00));
                    v01 = (v01 > 20.f) ? v01 : log1pf(__expf(v01));
                    v10 = (v10 > 20.f) ? v10 : log1pf(__expf(v10));
                    v11 = (v11 > 20.f) ? v11 : log1pf(__expf(v11));
                    v00 = fminf(fmaxf(v00, 0.001f), 0.1f);
                    v01 = fminf(fmaxf(v01, 0.001f), 0.1f);
                    v10 = fminf(fmaxf(v10, 0.001f), 0.1f);
                    v11 = fminf(fmaxf(v11, 0.001f), 0.1f);
                    rs[mt][0] += v00 + v01;
                    rs[mt][1] += v10 + v11;
                }
                *(float2*)(C + (size_t)row * ldc + col) = make_float2(v00, v01);
                *(float2*)(C + (size_t)(row + 8) * ldc + col) = make_float2(v10, v11);
            }
        }
    }

    if (EPI == 1) {
        #pragma unroll
        for (int mt = 0; mt < 2; mt++)
            #pragma unroll
            for (int hh = 0; hh < 2; hh++) {
                rs[mt][hh] += __shfl_xor_sync(0xffffffffu, rs[mt][hh], 1);
                rs[mt][hh] += __shfl_xor_sync(0xffffffffu, rs[mt][hh], 2);
            }
        __syncthreads();
        float* sred = (float*)sm;
        if ((lane & 3) == 0) {
            int rb = wm + (lane >> 2);
            int g = (wid >> 2) * 128;
            sred[g + rb]      = rs[0][0];
            sred[g + rb + 8]  = rs[0][1];
            sred[g + rb + 16] = rs[1][0];
            sred[g + rb + 24] = rs[1][1];
        }
        __syncthreads();
        if (tid < 128)
            part[(size_t)blockIdx.x * TOK + m0 + tid] = sred[tid] + sred[128 + tid];
    }
}

// ======================= 128x64 warp-MMA GEMM (3-stage) ======================
#define NBN    64
#define NBUFE  ((BM + NBN) * LDSTR)
#define NSTGB  (NBUFE * 2)            // 27648 B

__global__ void __launch_bounds__(256, 2)
gemm_n64(const __half* __restrict__ A, const __half* __restrict__ B,
         const float* __restrict__ bias, float* __restrict__ C,
         int K, int ldc) {
    extern __shared__ __align__(16) __half sm[];
    const uint32_t smb = smem_u32(sm);

    const int tid = threadIdx.x;
    const int lane = tid & 31, wid = tid >> 5;
    const int m0 = blockIdx.y * BM, n0 = blockIdx.x * NBN;
    const int wm = (wid & 3) * 32;
    const int wn = (wid >> 2) * 32;

    float acc[2][4][4];
    #pragma unroll
    for (int i = 0; i < 2; i++)
        #pragma unroll
        for (int j = 0; j < 4; j++)
            #pragma unroll
            for (int k = 0; k < 4; k++) acc[i][j][k] = 0.f;

    const int nc = K >> 6;

    auto load_tile = [&](int stg, int kc) {
        const __half* Ag = A + (size_t)m0 * K + kc * BKE;
        const __half* Bg = B + (size_t)n0 * K + kc * BKE;
        uint32_t sa = smb + stg * NSTGB;
        uint32_t sbb = sa + BM * LDSTR * 2;
        #pragma unroll
        for (int i = 0; i < 4; i++) {
            int ci = tid + i * 256;
            int row = ci >> 3, c8 = ci & 7;
            uint32_t so = (uint32_t)(row * LDSTR + c8 * 8) * 2;
            cp16(sa + so, Ag + (size_t)row * K + c8 * 8);
        }
        #pragma unroll
        for (int i = 0; i < 2; i++) {
            int ci = tid + i * 256;
            int row = ci >> 3, c8 = ci & 7;
            uint32_t so = (uint32_t)(row * LDSTR + c8 * 8) * 2;
            cp16(sbb + so, Bg + (size_t)row * K + c8 * 8);
        }
    };

    load_tile(0, 0);
    CP_COMMIT();
    if (nc > 1) load_tile(1, 1);
    CP_COMMIT();

    int cs = 0, ls = 2;
    for (int c = 0; c < nc; c++) {
        CP_WAIT1();
        __syncthreads();
        if (c + 2 < nc) {
            load_tile(ls, c + 2);
            ls = (ls + 1 == NSTG) ? 0 : ls + 1;
        }
        CP_COMMIT();

        const uint32_t a_base = smb + cs * NSTGB;
        const uint32_t b_base = a_base + BM * LDSTR * 2;

        #pragma unroll
        for (int kk = 0; kk < 4; kk++) {
            uint32_t afr[2][4];
            #pragma unroll
            for (int mt = 0; mt < 2; mt++) {
                int row = wm + mt * 16 + (lane & 15);
                int col = kk * 16 + (lane >> 4) * 8;
                ldsm_x4(afr[mt], a_base + (uint32_t)(row * LDSTR + col) * 2);
            }
            uint32_t bfr[4][2];
            #pragma unroll
            for (int p = 0; p < 2; p++) {
                int g = lane >> 3, idx = lane & 7;
                int row = wn + p * 16 + idx + (g >> 1) * 8;
                int col = kk * 16 + (g & 1) * 8;
                uint32_t r[4];
                ldsm_x4(r, b_base + (uint32_t)(row * LDSTR + col) * 2);
                bfr[2 * p][0] = r[0];     bfr[2 * p][1] = r[1];
                bfr[2 * p + 1][0] = r[2]; bfr[2 * p + 1][1] = r[3];
            }
            #pragma unroll
            for (int mt = 0; mt < 2; mt++)
                #pragma unroll
                for (int nt = 0; nt < 4; nt++)
                    mma_f16(acc[mt][nt], afr[mt], bfr[nt]);
        }
        cs = (cs + 1 == NSTG) ? 0 : cs + 1;
    }

    #pragma unroll
    for (int mt = 0; mt < 2; mt++) {
        #pragma unroll
        for (int nt = 0; nt < 4; nt++) {
            int row = m0 + wm + mt * 16 + (lane >> 2);
            int col = n0 + wn + nt * 8 + (lane & 3) * 2;
            float b0 = bias[col], b1 = bias[col + 1];
            *(float2*)(C + (size_t)row * ldc + col) =
                make_float2(acc[mt][nt][0] + b0, acc[mt][nt][1] + b1);
            *(float2*)(C + (size_t)(row + 8) * ldc + col) =
                make_float2(acc[mt][nt][2] + b0, acc[mt][nt][3] + b1);
        }
    }
}

// ======================= weight conversion, smem tile transpose ==============
// W[K,N] fp32 -> Bo[N,K] fp16. 64x64 tiles, coalesced reads AND writes.
__global__ void __launch_bounds__(256)
wconv_k(const float* __restrict__ W, __half* __restrict__ Bo, int N, int K) {
    __shared__ __half st[64][66];
    const int tid = threadIdx.x;
    const int n0 = blockIdx.x * 64;
    const int k0 = blockIdx.y * 64;

    #pragma unroll 4
    for (int idx = tid; idx < 64 * 64; idx += 256) {
        int kk = idx >> 6, nn = idx & 63;
        st[nn][kk] = __float2half(W[(size_t)(k0 + kk) * N + n0 + nn]);
    }
    __syncthreads();
    #pragma unroll 4
    for (int idx = tid; idx < 64 * 64; idx += 256) {
        int nn = idx >> 6, kk = idx & 63;
        Bo[(size_t)(n0 + nn) * K + k0 + kk] = st[nn][kk];
    }
}

// ======================= fp32 bc+dtr projection (+ fp16 dtr emit) ===========
__global__ void __launch_bounds__(256)
bcproj_k(const float* __restrict__ xa,
         const float* __restrict__ bcw, const float* __restrict__ dtw,
         const float* __restrict__ bcb, const float* __restrict__ dtrb,
         float* __restrict__ outp, __half* __restrict__ dtr16) {
    __shared__ float sW[64][100];
    __shared__ float sA[16][65];
    const int tid = threadIdx.x;
    const int r = tid >> 4, jg = tid & 15;
    const int m0 = blockIdx.x * 16;

    float acc[6];
    #pragma unroll
    for (int c = 0; c < 6; c++) acc[c] = 0.f;

    for (int k0 = 0; k0 < INNER; k0 += 64) {
        __syncthreads();
        for (int idx = tid; idx < 64 * 96; idx += 256) {
            int kl = idx / 96, j = idx % 96;
            float v = (j < 32) ? bcw[(size_t)(k0 + kl) * 32 + j]
                               : dtw[(size_t)(k0 + kl) * 64 + (j - 32)];
            sW[kl][j] = v;
        }
        for (int idx = tid; idx < 16 * 64; idx += 256) {
            int rr = idx >> 6, kl = idx & 63;
            sA[rr][kl] = xa[(size_t)(m0 + rr) * INNER + k0 + kl];
        }
        __syncthreads();
        #pragma unroll 8
        for (int kl = 0; kl < 64; kl++) {
            float a = sA[r][kl];
            const float* wrow = &sW[kl][jg * 6];
            float2 w01 = *(const float2*)(wrow);
            float2 w23 = *(const float2*)(wrow + 2);
            float2 w45 = *(const float2*)(wrow + 4);
            acc[0] = fmaf(a, w01.x, acc[0]);
            acc[1] = fmaf(a, w01.y, acc[1]);
            acc[2] = fmaf(a, w23.x, acc[2]);
            acc[3] = fmaf(a, w23.y, acc[3]);
            acc[4] = fmaf(a, w45.x, acc[4]);
            acc[5] = fmaf(a, w45.y, acc[5]);
        }
    }
    #pragma unroll
    for (int c = 0; c < 6; c++) {
        int j = jg * 6 + c;
        float bv = (j < 32) ? bcb[j] : dtrb[j - 32];
        float v = acc[c] + bv;
        outp[(size_t)(m0 + r) * 96 + j] = v;
        if (j >= 32)
            dtr16[(size_t)(m0 + r) * 64 + (j - 32)] = __float2half(v);
    }
}

// ======================= LayerNorm (warp per row) -> fp16 A ==================
__global__ void __launch_bounds__(256)
layernorm_h_k(const float* __restrict__ x,
              const float* __restrict__ w,
              const float* __restrict__ b,
              __half* __restrict__ Ao) {
    const int lane = threadIdx.x & 31;
    const int row = blockIdx.x * 8 + (threadIdx.x >> 5);
    const float* xr = x + (size_t)row * H;

    float4 v[8];
    float s = 0.f, s2 = 0.f;
    #pragma unroll
    for (int i = 0; i < 8; i++) {
        v[i] = *(const float4*)(xr + (i * 32 + lane) * 4);
        s  += (v[i].x + v[i].y) + (v[i].z + v[i].w);
        s2 += v[i].x * v[i].x + v[i].y * v[i].y + v[i].z * v[i].z + v[i].w * v[i].w;
    }
    #pragma unroll
    for (int o = 16; o > 0; o >>= 1) {
        s  += __shfl_xor_sync(0xffffffffu, s,  o);
        s2 += __shfl_xor_sync(0xffffffffu, s2, o);
    }
    float mu = s / (float)H;
    float rstd = rsqrtf(s2 / (float)H - mu * mu + 1e-5f);

    #pragma unroll
    for (int i = 0; i < 8; i++) {
        int c = (i * 32 + lane) * 4;
        __half2 h0 = __floats2half2_rn((v[i].x - mu) * rstd * w[c]     + b[c],
                                       (v[i].y - mu) * rstd * w[c + 1] + b[c + 1]);
        __half2 h1 = __floats2half2_rn((v[i].z - mu) * rstd * w[c + 2] + b[c + 2],
                                       (v[i].w - mu) * rstd * w[c + 3] + b[c + 3]);
        *(__half2*)(Ao + (size_t)row * H + c)     = h0;
        *(__half2*)(Ao + (size_t)row * H + c + 2) = h1;
    }
}

// ======================= conv(4-tap)+SiLU, time-tiled in smem ================
// block: 64 channels x 128 tokens; loads (128+3) x 64 patch once.
#define CCT 128
#define CCD 64
__global__ void __launch_bounds__(256)
conv_silu_k(const float* __restrict__ xz,
            const float* __restrict__ cw,
            const float* __restrict__ cb,
            float* __restrict__ xa) {
    __shared__ float sxz[(CCT + 3) * CCD];
    const int tid = threadIdx.x;
    const int d0 = blockIdx.x * CCD;
    const int t0 = blockIdx.y * CCT;
    const int b  = blockIdx.z;

    for (int idx = tid; idx < (CCT + 3) * (CCD / 4); idx += 256) {
        int rr = idx / (CCD / 4);
        int cc = (idx % (CCD / 4)) * 4;
        int tt = t0 - 3 + rr;
        float4 v = make_float4(0.f, 0.f, 0.f, 0.f);
        if (tt >= 0)
            v = *(const float4*)(xz + (size_t)(b * SEQ + tt) * (2 * INNER) + d0 + cc);
        *(float4*)&sxz[rr * CCD + cc] = v;
    }
    __syncthreads();

    const int c = tid & (CCD - 1);
    const int tq0 = (tid >> 6) * 32;
    float4 w4 = *(const float4*)(cw + (d0 + c) * 4);
    float bias = cb[d0 + c];

    #pragma unroll
    for (int q = 0; q < 32; q++) {
        int r = tq0 + q;
        float acc = bias;
        acc = fmaf(sxz[(r + 0) * CCD + c], w4.x, acc);
        acc = fmaf(sxz[(r + 1) * CCD + c], w4.y, acc);
        acc = fmaf(sxz[(r + 2) * CCD + c], w4.z, acc);
        acc = fmaf(sxz[(r + 3) * CCD + c], w4.w, acc);
        float o = acc / (1.f + __expf(-acc));
        xa[(size_t)(b * SEQ + t0 + r) * INNER + d0 + c] = o;
    }
}

// ======================= mean finalize (16 partials per token) ===============
__global__ void meanfin_k(const float* __restrict__ part, float* __restrict__ m) {
    int t = blockIdx.x * 256 + threadIdx.x;
    float s = 0.f;
    #pragma unroll
    for (int j = 0; j < 16; j++)
        s += part[(size_t)j * TOK + t];
    m[t] = s * (1.f / (float)INNER);
}

// ======================= segmented parallel scan + gating ====================
#define SEGS   16
#define SEGLEN 64

__device__ __forceinline__ void pow_ladder(float e1, float* p) {
    float e2 = e1 * e1, e4 = e2 * e2, e8 = e4 * e4;
    p[0] = e1;       p[1] = e2;       p[2] = e2 * e1;  p[3] = e4;
    p[4] = e4 * e1;  p[5] = e4 * e2;  p[6] = e4 * p[2]; p[7] = e8;
    p[8] = e8 * e1;  p[9] = e8 * e2;  p[10] = e8 * p[2]; p[11] = e8 * e4;
    p[12] = e8 * p[4]; p[13] = e8 * p[5]; p[14] = e8 * p[6]; p[15] = e8 * e8;
}

__global__ void __launch_bounds__(512)
scan_k(const float* __restrict__ dt,
       const float* __restrict__ xa,
       const float* __restrict__ dtmean,
       const float* __restrict__ bcdtr,
       const float* __restrict__ xz,
       __half* __restrict__ Ao) {
    __shared__ float shH[SEGS][32][NST];
    __shared__ float shS[SEGS][32];

    const int tid = threadIdx.x;
    const int dlane = tid & 31, s = tid >> 5;
    const int b = blockIdx.y;
    const int d = blockIdx.x * 32 + dlane;
    const int t0 = b * SEQ + s * SEGLEN;

    float h[NST];
    #pragma unroll
    for (int n = 0; n < NST; n++) h[n] = 0.f;
    float sdt = 0.f;

    #pragma unroll 2
    for (int i = 0; i < SEGLEN; i++) {
        const int t = t0 + i;
        float dtv = dt[(size_t)t * INNER + d];
        float xav = xa[(size_t)t * INNER + d];
        float dm  = dtmean[t];
        float bx  = dm * xav;
        sdt += dtv;
        float p[NST];
        pow_ladder(__expf(-dtv), p);
        const float4* bp = (const float4*)(bcdtr + (size_t)t * 96);
        float4 b0 = bp[0], b1 = bp[1], b2 = bp[2], b3 = bp[3];
        float Bm[NST] = {b0.x, b0.y, b0.z, b0.w, b1.x, b1.y, b1.z, b1.w,
                         b2.x, b2.y, b2.z, b2.w, b3.x, b3.y, b3.z, b3.w};
        #pragma unroll
        for (int n = 0; n < NST; n++)
            h[n] = fmaf(p[n], h[n], bx * Bm[n]);
    }
    shS[s][dlane] = sdt;
    #pragma unroll
    for (int n = 0; n < NST; n++) shH[s][dlane][n] = h[n];
    __syncthreads();

    float hin[NST];
    #pragma unroll
    for (int n = 0; n < NST; n++) hin[n] = 0.f;
    for (int j = 0; j < s; j++) {
        float p[NST];
        pow_ladder(__expf(-shS[j][dlane]), p);
        #pragma unroll
        for (int n = 0; n < NST; n++)
            hin[n] = fmaf(p[n], hin[n], shH[j][dlane][n]);
    }

    #pragma unroll
    for (int n = 0; n < NST; n++) h[n] = hin[n];

    #pragma unroll 2
    for (int i = 0; i < SEGLEN; i++) {
        const int t = t0 + i;
        float dtv = dt[(size_t)t * INNER + d];
        float xav = xa[(size_t)t * INNER + d];
        float zv  = xz[(size_t)t * (2 * INNER) + INNER + d];
        float dm  = dtmean[t];
        float bx  = dm * xav;
        float p[NST];
        pow_ladder(__expf(-dtv), p);
        const float4* bp = (const float4*)(bcdtr + (size_t)t * 96);
        float4 b0 = bp[0], b1 = bp[1], b2 = bp[2], b3 = bp[3];
        float4 c0 = bp[4], c1 = bp[5], c2 = bp[6], c3 = bp[7];
        float Bm[NST] = {b0.x, b0.y, b0.z, b0.w, b1.x, b1.y, b1.z, b1.w,
                         b2.x, b2.y, b2.z, b2.w, b3.x, b3.y, b3.z, b3.w};
        float Cm[NST] = {c0.x, c0.y, c0.z, c0.w, c1.x, c1.y, c1.z, c1.w,
                         c2.x, c2.y, c2.z, c2.w, c3.x, c3.y, c3.z, c3.w};
        float y0 = 0.f, y1 = 0.f, y2 = 0.f, y3 = 0.f;
        #pragma unroll
        for (int n = 0; n < NST; n += 4) {
            h[n + 0] = fmaf(p[n + 0], h[n + 0], bx * Bm[n + 0]);
            h[n + 1] = fmaf(p[n + 1], h[n + 1], bx * Bm[n + 1]);
            h[n + 2] = fmaf(p[n + 2], h[n + 2], bx * Bm[n + 2]);
            h[n + 3] = fmaf(p[n + 3], h[n + 3], bx * Bm[n + 3]);
            y0 = fmaf(h[n + 0], Cm[n + 0], y0);
            y1 = fmaf(h[n + 1], Cm[n + 1], y1);
            y2 = fmaf(h[n + 2], Cm[n + 2], y2);
            y3 = fmaf(h[n + 3], Cm[n + 3], y3);
        }
        float y = (y0 + y1) + (y2 + y3);
        float sz = zv / (1.f + __expf(-zv));
        Ao[(size_t)t * INNER + d] = __float2half(y * sz);
    }
}

// ======================= launch =============================================
extern "C" void kernel_launch(void* const* d_in, const int* in_sizes, int n_in,
                              void* d_out, int out_size) {
    const float* x      = (const float*)d_in[0];
    const float* norm_w = (const float*)d_in[1];
    const float* norm_b = (const float*)d_in[2];
    const float* in_w   = (const float*)d_in[3];
    const float* in_b   = (const float*)d_in[4];
    const float* conv_w = (const float*)d_in[5];
    const float* conv_b = (const float*)d_in[6];
    const float* bc_w   = (const float*)d_in[7];
    const float* bc_b   = (const float*)d_in[8];
    const float* dtr_w  = (const float*)d_in[9];
    const float* dtr_b  = (const float*)d_in[10];
    const float* dt_w   = (const float*)d_in[11];
    const float* dt_b   = (const float*)d_in[12];
    const float* out_w  = (const float*)d_in[13];
    const float* out_b  = (const float*)d_in[14];
    float* out = (float*)d_out;

    __half *pA_in, *pB_in, *pA_dtr, *pB_dt, *pA_out, *pB_out;
    float *pxz, *pxa, *pbcdtr, *pdt, *pdtpart, *pdtm;
    cudaGetSymbolAddress((void**)&pA_in,   gA_in);
    cudaGetSymbolAddress((void**)&pB_in,   gB_in);
    cudaGetSymbolAddress((void**)&pxz,     g_xz);
    cudaGetSymbolAddress((void**)&pxa,     g_xa);
    cudaGetSymbolAddress((void**)&pbcdtr,  g_bcdtr);
    cudaGetSymbolAddress((void**)&pA_dtr,  gA_dtr);
    cudaGetSymbolAddress((void**)&pB_dt,   gB_dt);
    cudaGetSymbolAddress((void**)&pdt,     g_dt);
    cudaGetSymbolAddress((void**)&pdtpart, g_dtpart);
    cudaGetSymbolAddress((void**)&pdtm,    g_dtmean);
    cudaGetSymbolAddress((void**)&pA_out,  gA_out);
    cudaGetSymbolAddress((void**)&pB_out,  gB_out);

    const int DSMEM  = NSTG * STGB;    // 110592
    const int DSMEMN = NSTG * NSTGB;   // 82944
    cudaFuncSetAttribute(gemm_h<0>, cudaFuncAttributeMaxDynamicSharedMemorySize, DSMEM);
    cudaFuncSetAttribute(gemm_h<1>, cudaFuncAttributeMaxDynamicSharedMemorySize, DSMEM);
    cudaFuncSetAttribute(gemm_n64, cudaFuncAttributeMaxDynamicSharedMemorySize, DSMEMN);

    // 1. LayerNorm -> fp16 A (warp per row)
    layernorm_h_k<<<TOK / 8, 256>>>(x, norm_w, norm_b, pA_in);
    // 2-3. weight conversions (tiled transpose, coalesced)
    wconv_k<<<dim3((2 * INNER) / 64, H / 64), 256>>>(in_w, pB_in, 2 * INNER, H);
    wconv_k<<<dim3(INNER / 64, DTR / 64), 256>>>(dt_w, pB_dt, INNER, DTR);
    // 4. in-proj GEMM (M=2048, N=4096, K=1024)  <-- ncu capture slot
    gemm_h<0><<<dim3(4096 / 128, TOK / 128), 256, DSMEM>>>(
        pA_in, pB_in, in_b, pxz, nullptr, H, 2 * INNER, 2 * INNER);
    // 5. conv + SiLU (time-tiled smem, 128 tokens) -> xa fp32
    conv_silu_k<<<dim3(INNER / CCD, SEQ / CCT, BATCH), 256>>>(pxz, conv_w, conv_b, pxa);
    // 6. fp32 bc + dtr projection, fused fp16 dtr emit
    bcproj_k<<<TOK / 16, 256>>>(pxa, bc_w, dtr_w, bc_b, dtr_b, pbcdtr, pA_dtr);
    // 7. dt GEMM (M=2048, N=2048, K=64): softplus+clip + per-CTA row sums
    gemm_h<1><<<dim3(INNER / 128, TOK / 128), 256, DSMEM>>>(
        pA_dtr, pB_dt, dt_b, pdt, pdtpart, DTR, INNER, INNER);
    // 8. mean finalize
    meanfin_k<<<TOK / 256, 256>>>(pdtpart, pdtm);
    // 9. segmented parallel scan + gating -> fp16 A
    scan_k<<<dim3(INNER / 32, BATCH), 512>>>(pdt, pxa, pdtm, pbcdtr, pxz, pA_out);
    // 10. out-proj weight conversion
    wconv_k<<<dim3(H / 64, INNER / 64), 256>>>(out_w, pB_out, H, INNER);
    // 11. out-proj GEMM (M=2048, N=1024, K=2048), 128x64 tiles
    gemm_n64<<<dim3(H / NBN, TOK / BM), 256, DSMEMN>>>(
        pA_out, pB_out, out_b, out, INNER, H);
}

// round 16
// speedup vs baseline: 1.2806x; 1.2806x over previous
#include <cuda_runtime.h>
#include <cuda_fp16.h>
#include <cstdint>
#include <math.h>

#define H      1024
#define INNER  2048
#define NST    16
#define DTR    64
#define BATCH  2
#define SEQ    1024
#define TOK    (BATCH*SEQ)   // 2048

// ======================= PTX helpers (plain sm_103 legal) ====================
__device__ __forceinline__ uint32_t smem_u32(const void* p) {
    uint32_t a;
    asm("{ .reg .u64 t; cvta.to.shared.u64 t, %1; cvt.u32.u64 %0, t; }"
        : "=r"(a) : "l"(p));
    return a;
}
__device__ __forceinline__ void cp16(uint32_t saddr, const void* g) {
    asm volatile("cp.async.cg.shared.global [%0], [%1], 16;"
                 :: "r"(saddr), "l"(g) : "memory");
}
#define CP_COMMIT() asm volatile("cp.async.commit_group;" ::: "memory")
#define CP_WAIT1()  asm volatile("cp.async.wait_group 1;" ::: "memory")

__device__ __forceinline__ void ldsm_x4(uint32_t* r, uint32_t addr) {
    asm volatile("ldmatrix.sync.aligned.m8n8.x4.shared.b16 {%0,%1,%2,%3}, [%4];"
                 : "=r"(r[0]), "=r"(r[1]), "=r"(r[2]), "=r"(r[3]) : "r"(addr));
}
__device__ __forceinline__ void mma_f16(float* c, const uint32_t* a, const uint32_t* b) {
    asm volatile("mma.sync.aligned.m16n8k16.row.col.f32.f16.f16.f32 "
                 "{%0,%1,%2,%3}, {%4,%5,%6,%7}, {%8,%9}, {%0,%1,%2,%3};"
                 : "+f"(c[0]), "+f"(c[1]), "+f"(c[2]), "+f"(c[3])
                 : "r"(a[0]), "r"(a[1]), "r"(a[2]), "r"(a[3]),
                   "r"(b[0]), "r"(b[1]));
}

// ======================= scratch buffers ====================================
__device__ __align__(16) __half gA_in [TOK * H];
__device__ __align__(16) __half gB_in [2 * INNER * H];
__device__ __align__(16) float  g_xz  [TOK * 2 * INNER];
__device__ __align__(16) float  g_xa  [TOK * INNER];
__device__ __align__(16) float  g_bcpart[4 * TOK * 96];   // split-K partials
__device__ __align__(16) float  g_bcdtr[TOK * 96];
__device__ __align__(16) __half gA_dtr[TOK * DTR];
__device__ __align__(16) __half gB_dt [INNER * DTR];
__device__ __align__(16) float  g_dt  [TOK * INNER];
__device__ __align__(16) float  g_dtpart[16 * TOK];
__device__                float g_dtmean[TOK];
__device__ __align__(16) __half gA_out[TOK * INNER];
__device__ __align__(16) __half gB_out[H * INNER];

#define LDSTR 72

// ======================= 128x128 warp-MMA GEMM (3-stage) =====================
#define BM    128
#define BN    128
#define BKE   64
#define BUFE  ((BM + BN) * LDSTR)
#define STGB  (BUFE * 2)             // 36864 B
#define NSTG  3

template <int EPI>
__global__ void __launch_bounds__(256, 2)
gemm_h(const __half* __restrict__ A, const __half* __restrict__ B,
       const float* __restrict__ bias, float* __restrict__ C,
       float* __restrict__ part,
       int K, int ldc, int nvalid) {
    extern __shared__ __align__(16) __half sm[];
    const uint32_t smb = smem_u32(sm);

    const int tid = threadIdx.x;
    const int lane = tid & 31, wid = tid >> 5;
    const int m0 = blockIdx.y * BM, n0 = blockIdx.x * BN;
    const int wm = (wid & 3) * 32;
    const int wn = (wid >> 2) * 64;

    float acc[2][8][4];
    #pragma unroll
    for (int i = 0; i < 2; i++)
        #pragma unroll
        for (int j = 0; j < 8; j++)
            #pragma unroll
            for (int k = 0; k < 4; k++) acc[i][j][k] = 0.f;

    const int nc = K >> 6;

    auto load_tile = [&](int stg, int kc) {
        const __half* Ag = A + (size_t)m0 * K + kc * BKE;
        const __half* Bg = B + (size_t)n0 * K + kc * BKE;
        uint32_t sa = smb + stg * STGB;
        uint32_t sbb = sa + BM * LDSTR * 2;
        #pragma unroll
        for (int i = 0; i < 4; i++) {
            int ci = tid + i * 256;
            int row = ci >> 3, c8 = ci & 7;
            uint32_t so = (uint32_t)(row * LDSTR + c8 * 8) * 2;
            cp16(sa + so,  Ag + (size_t)row * K + c8 * 8);
            cp16(sbb + so, Bg + (size_t)row * K + c8 * 8);
        }
    };

    load_tile(0, 0);
    CP_COMMIT();
    if (nc > 1) load_tile(1, 1);
    CP_COMMIT();

    int cs = 0, ls = 2;
    for (int c = 0; c < nc; c++) {
        CP_WAIT1();
        __syncthreads();
        if (c + 2 < nc) {
            load_tile(ls, c + 2);
            ls = (ls + 1 == NSTG) ? 0 : ls + 1;
        }
        CP_COMMIT();

        const uint32_t a_base = smb + cs * STGB;
        const uint32_t b_base = a_base + BM * LDSTR * 2;

        #pragma unroll
        for (int kk = 0; kk < 4; kk++) {
            uint32_t afr[2][4];
            #pragma unroll
            for (int mt = 0; mt < 2; mt++) {
                int row = wm + mt * 16 + (lane & 15);
                int col = kk * 16 + (lane >> 4) * 8;
                ldsm_x4(afr[mt], a_base + (uint32_t)(row * LDSTR + col) * 2);
            }
            uint32_t bfr[8][2];
            #pragma unroll
            for (int p = 0; p < 4; p++) {
                int g = lane >> 3, idx = lane & 7;
                int row = wn + p * 16 + idx + (g >> 1) * 8;
                int col = kk * 16 + (g & 1) * 8;
                uint32_t r[4];
                ldsm_x4(r, b_base + (uint32_t)(row * LDSTR + col) * 2);
                bfr[2 * p][0] = r[0];     bfr[2 * p][1] = r[1];
                bfr[2 * p + 1][0] = r[2]; bfr[2 * p + 1][1] = r[3];
            }
            #pragma unroll
            for (int mt = 0; mt < 2; mt++)
                #pragma unroll
                for (int nt = 0; nt < 8; nt++)
                    mma_f16(acc[mt][nt], afr[mt], bfr[nt]);
        }
        cs = (cs + 1 == NSTG) ? 0 : cs + 1;
    }

    float rs[2][2] = {{0.f, 0.f}, {0.f, 0.f}};

    #pragma unroll
    for (int mt = 0; mt < 2; mt++) {
        #pragma unroll
        for (int nt = 0; nt < 8; nt++) {
            int row = m0 + wm + mt * 16 + (lane >> 2);
            int col = n0 + wn + nt * 8 + (lane & 3) * 2;
            if (col < nvalid) {
                float b0 = bias[col], b1 = bias[col + 1];
                float v00 = acc[mt][nt][0] + b0, v01 = acc[mt][nt][1] + b1;
                float v10 = acc[mt][nt][2] + b0, v11 = acc[mt][nt][3] + b1;
                if (EPI == 1) {
                    v00 = (v00 > 20.f) ? v00 : log1pf(__expf(v00));
                    v01 = (v01 > 20.f) ? v01 : log1pf(__expf(v01));
                    v10 = (v10 > 20.f) ? v10 : log1pf(__expf(v10));
                    v11 = (v11 > 20.f) ? v11 : log1pf(__expf(v11));
                    v00 = fminf(fmaxf(v00, 0.001f), 0.1f);
                    v01 = fminf(fmaxf(v01, 0.001f), 0.1f);
                    v10 = fminf(fmaxf(v10, 0.001f), 0.1f);
                    v11 = fminf(fmaxf(v11, 0.001f), 0.1f);
                    rs[mt][0] += v00 + v01;
                    rs[mt][1] += v10 + v11;
                }
                *(float2*)(C + (size_t)row * ldc + col) = make_float2(v00, v01);
                *(float2*)(C + (size_t)(row + 8) * ldc + col) = make_float2(v10, v11);
            }
        }
    }

    if (EPI == 1) {
        #pragma unroll
        for (int mt = 0; mt < 2; mt++)
            #pragma unroll
            for (int hh = 0; hh < 2; hh++) {
                rs[mt][hh] += __shfl_xor_sync(0xffffffffu, rs[mt][hh], 1);
                rs[mt][hh] += __shfl_xor_sync(0xffffffffu, rs[mt][hh], 2);
            }
        __syncthreads();
        float* sred = (float*)sm;
        if ((lane & 3) == 0) {
            int rb = wm + (lane >> 2);
            int g = (wid >> 2) * 128;
            sred[g + rb]      = rs[0][0];
            sred[g + rb + 8]  = rs[0][1];
            sred[g + rb + 16] = rs[1][0];
            sred[g + rb + 24] = rs[1][1];
        }
        __syncthreads();
        if (tid < 128)
            part[(size_t)blockIdx.x * TOK + m0 + tid] = sred[tid] + sred[128 + tid];
    }
}

// ======================= 128x64 warp-MMA GEMM (3-stage) ======================
#define NBN    64
#define NBUFE  ((BM + NBN) * LDSTR)
#define NSTGB  (NBUFE * 2)            // 27648 B

__global__ void __launch_bounds__(256, 2)
gemm_n64(const __half* __restrict__ A, const __half* __restrict__ B,
         const float* __restrict__ bias, float* __restrict__ C,
         int K, int ldc) {
    extern __shared__ __align__(16) __half sm[];
    const uint32_t smb = smem_u32(sm);

    const int tid = threadIdx.x;
    const int lane = tid & 31, wid = tid >> 5;
    const int m0 = blockIdx.y * BM, n0 = blockIdx.x * NBN;
    const int wm = (wid & 3) * 32;
    const int wn = (wid >> 2) * 32;

    float acc[2][4][4];
    #pragma unroll
    for (int i = 0; i < 2; i++)
        #pragma unroll
        for (int j = 0; j < 4; j++)
            #pragma unroll
            for (int k = 0; k < 4; k++) acc[i][j][k] = 0.f;

    const int nc = K >> 6;

    auto load_tile = [&](int stg, int kc) {
        const __half* Ag = A + (size_t)m0 * K + kc * BKE;
        const __half* Bg = B + (size_t)n0 * K + kc * BKE;
        uint32_t sa = smb + stg * NSTGB;
        uint32_t sbb = sa + BM * LDSTR * 2;
        #pragma unroll
        for (int i = 0; i < 4; i++) {
            int ci = tid + i * 256;
            int row = ci >> 3, c8 = ci & 7;
            uint32_t so = (uint32_t)(row * LDSTR + c8 * 8) * 2;
            cp16(sa + so, Ag + (size_t)row * K + c8 * 8);
        }
        #pragma unroll
        for (int i = 0; i < 2; i++) {
            int ci = tid + i * 256;
            int row = ci >> 3, c8 = ci & 7;
            uint32_t so = (uint32_t)(row * LDSTR + c8 * 8) * 2;
            cp16(sbb + so, Bg + (size_t)row * K + c8 * 8);
        }
    };

    load_tile(0, 0);
    CP_COMMIT();
    if (nc > 1) load_tile(1, 1);
    CP_COMMIT();

    int cs = 0, ls = 2;
    for (int c = 0; c < nc; c++) {
        CP_WAIT1();
        __syncthreads();
        if (c + 2 < nc) {
            load_tile(ls, c + 2);
            ls = (ls + 1 == NSTG) ? 0 : ls + 1;
        }
        CP_COMMIT();

        const uint32_t a_base = smb + cs * NSTGB;
        const uint32_t b_base = a_base + BM * LDSTR * 2;

        #pragma unroll
        for (int kk = 0; kk < 4; kk++) {
            uint32_t afr[2][4];
            #pragma unroll
            for (int mt = 0; mt < 2; mt++) {
                int row = wm + mt * 16 + (lane & 15);
                int col = kk * 16 + (lane >> 4) * 8;
                ldsm_x4(afr[mt], a_base + (uint32_t)(row * LDSTR + col) * 2);
            }
            uint32_t bfr[4][2];
            #pragma unroll
            for (int p = 0; p < 2; p++) {
                int g = lane >> 3, idx = lane & 7;
                int row = wn + p * 16 + idx + (g >> 1) * 8;
                int col = kk * 16 + (g & 1) * 8;
                uint32_t r[4];
                ldsm_x4(r, b_base + (uint32_t)(row * LDSTR + col) * 2);
                bfr[2 * p][0] = r[0];     bfr[2 * p][1] = r[1];
                bfr[2 * p + 1][0] = r[2]; bfr[2 * p + 1][1] = r[3];
            }
            #pragma unroll
            for (int mt = 0; mt < 2; mt++)
                #pragma unroll
                for (int nt = 0; nt < 4; nt++)
                    mma_f16(acc[mt][nt], afr[mt], bfr[nt]);
        }
        cs = (cs + 1 == NSTG) ? 0 : cs + 1;
    }

    #pragma unroll
    for (int mt = 0; mt < 2; mt++) {
        #pragma unroll
        for (int nt = 0; nt < 4; nt++) {
            int row = m0 + wm + mt * 16 + (lane >> 2);
            int col = n0 + wn + nt * 8 + (lane & 3) * 2;
            float b0 = bias[col], b1 = bias[col + 1];
            *(float2*)(C + (size_t)row * ldc + col) =
                make_float2(acc[mt][nt][0] + b0, acc[mt][nt][1] + b1);
            *(float2*)(C + (size_t)(row + 8) * ldc + col) =
                make_float2(acc[mt][nt][2] + b0, acc[mt][nt][3] + b1);
        }
    }
}

// ======================= weight conversion, smem tile transpose ==============
__global__ void __launch_bounds__(256)
wconv_k(const float* __restrict__ W, __half* __restrict__ Bo, int N, int K) {
    __shared__ __half st[64][66];
    const int tid = threadIdx.x;
    const int n0 = blockIdx.x * 64;
    const int k0 = blockIdx.y * 64;

    #pragma unroll 4
    for (int idx = tid; idx < 64 * 64; idx += 256) {
        int kk = idx >> 6, nn = idx & 63;
        st[nn][kk] = __float2half(W[(size_t)(k0 + kk) * N + n0 + nn]);
    }
    __syncthreads();
    #pragma unroll 4
    for (int idx = tid; idx < 64 * 64; idx += 256) {
        int nn = idx >> 6, kk = idx & 63;
        Bo[(size_t)(n0 + nn) * K + k0 + kk] = st[nn][kk];
    }
}

// ======================= fp32 bc+dtr projection, split-K ====================
// grid (TOK/16, 4 k-slices). Each block: 16 tokens x 96 cols over K/4 = 512.
__global__ void __launch_bounds__(256)
bcproj_k(const float* __restrict__ xa,
         const float* __restrict__ bcw, const float* __restrict__ dtw,
         float* __restrict__ part) {
    __shared__ float sW[64][100];
    __shared__ float sA[16][65];
    const int tid = threadIdx.x;
    const int r = tid >> 4, jg = tid & 15;
    const int m0 = blockIdx.x * 16;
    const int ks = blockIdx.y;
    const int kbeg = ks * (INNER / 4);

    float acc[6];
    #pragma unroll
    for (int c = 0; c < 6; c++) acc[c] = 0.f;

    for (int k0 = kbeg; k0 < kbeg + INNER / 4; k0 += 64) {
        __syncthreads();
        for (int idx = tid; idx < 64 * 96; idx += 256) {
            int kl = idx / 96, j = idx % 96;
            float v = (j < 32) ? bcw[(size_t)(k0 + kl) * 32 + j]
                               : dtw[(size_t)(k0 + kl) * 64 + (j - 32)];
            sW[kl][j] = v;
        }
        for (int idx = tid; idx < 16 * 64; idx += 256) {
            int rr = idx >> 6, kl = idx & 63;
            sA[rr][kl] = xa[(size_t)(m0 + rr) * INNER + k0 + kl];
        }
        __syncthreads();
        #pragma unroll 8
        for (int kl = 0; kl < 64; kl++) {
            float a = sA[r][kl];
            const float* wrow = &sW[kl][jg * 6];
            float2 w01 = *(const float2*)(wrow);
            float2 w23 = *(const float2*)(wrow + 2);
            float2 w45 = *(const float2*)(wrow + 4);
            acc[0] = fmaf(a, w01.x, acc[0]);
            acc[1] = fmaf(a, w01.y, acc[1]);
            acc[2] = fmaf(a, w23.x, acc[2]);
            acc[3] = fmaf(a, w23.y, acc[3]);
            acc[4] = fmaf(a, w45.x, acc[4]);
            acc[5] = fmaf(a, w45.y, acc[5]);
        }
    }
    #pragma unroll
    for (int c = 0; c < 6; c++) {
        int j = jg * 6 + c;
        part[((size_t)ks * TOK + m0 + r) * 96 + j] = acc[c];
    }
}

// combine 4 k-slice partials + bias; emit bcdtr fp32 and dtr fp16
__global__ void __launch_bounds__(256)
bccomb_k(const float* __restrict__ part,
         const float* __restrict__ bcb, const float* __restrict__ dtrb,
         float* __restrict__ outp, __half* __restrict__ dtr16) {
    int idx = blockIdx.x * 256 + threadIdx.x;   // over TOK*96
    int t = idx / 96, j = idx - t * 96;
    float s = part[(size_t)t * 96 + j]
            + part[((size_t)TOK + t) * 96 + j]
            + part[((size_t)2 * TOK + t) * 96 + j]
            + part[((size_t)3 * TOK + t) * 96 + j];
    float bv = (j < 32) ? bcb[j] : dtrb[j - 32];
    float v = s + bv;
    outp[(size_t)t * 96 + j] = v;
    if (j >= 32)
        dtr16[(size_t)t * 64 + (j - 32)] = __float2half(v);
}

// ======================= LayerNorm (warp per row) -> fp16 A ==================
__global__ void __launch_bounds__(256)
layernorm_h_k(const float* __restrict__ x,
              const float* __restrict__ w,
              const float* __restrict__ b,
              __half* __restrict__ Ao) {
    const int lane = threadIdx.x & 31;
    const int row = blockIdx.x * 8 + (threadIdx.x >> 5);
    const float* xr = x + (size_t)row * H;

    float4 v[8];
    float s = 0.f, s2 = 0.f;
    #pragma unroll
    for (int i = 0; i < 8; i++) {
        v[i] = *(const float4*)(xr + (i * 32 + lane) * 4);
        s  += (v[i].x + v[i].y) + (v[i].z + v[i].w);
        s2 += v[i].x * v[i].x + v[i].y * v[i].y + v[i].z * v[i].z + v[i].w * v[i].w;
    }
    #pragma unroll
    for (int o = 16; o > 0; o >>= 1) {
        s  += __shfl_xor_sync(0xffffffffu, s,  o);
        s2 += __shfl_xor_sync(0xffffffffu, s2, o);
    }
    float mu = s / (float)H;
    float rstd = rsqrtf(s2 / (float)H - mu * mu + 1e-5f);

    #pragma unroll
    for (int i = 0; i < 8; i++) {
        int c = (i * 32 + lane) * 4;
        __half2 h0 = __floats2half2_rn((v[i].x - mu) * rstd * w[c]     + b[c],
                                       (v[i].y - mu) * rstd * w[c + 1] + b[c + 1]);
        __half2 h1 = __floats2half2_rn((v[i].z - mu) * rstd * w[c + 2] + b[c + 2],
                                       (v[i].w - mu) * rstd * w[c + 3] + b[c + 3]);
        *(__half2*)(Ao + (size_t)row * H + c)     = h0;
        *(__half2*)(Ao + (size_t)row * H + c + 2) = h1;
    }
}

// ======================= conv(4-tap)+SiLU, time-tiled in smem ================
// R14 config: 64 channels x 64 tokens.
#define CCT 64
#define CCD 64
__global__ void __launch_bounds__(256)
conv_silu_k(const float* __restrict__ xz,
            const float* __restrict__ cw,
            const float* __restrict__ cb,
            float* __restrict__ xa) {
    __shared__ float sxz[(CCT + 3) * CCD];
    const int tid = threadIdx.x;
    const int d0 = blockIdx.x * CCD;
    const int t0 = blockIdx.y * CCT;
    const int b  = blockIdx.z;

    for (int idx = tid; idx < (CCT + 3) * (CCD / 4); idx += 256) {
        int rr = idx / (CCD / 4);
        int cc = (idx % (CCD / 4)) * 4;
        int tt = t0 - 3 + rr;
        float4 v = make_float4(0.f, 0.f, 0.f, 0.f);
        if (tt >= 0)
            v = *(const float4*)(xz + (size_t)(b * SEQ + tt) * (2 * INNER) + d0 + cc);
        *(float4*)&sxz[rr * CCD + cc] = v;
    }
    __syncthreads();

    const int c = tid & (CCD - 1);
    const int tq0 = (tid >> 6) * 16;
    float4 w4 = *(const float4*)(cw + (d0 + c) * 4);
    float bias = cb[d0 + c];

    #pragma unroll
    for (int q = 0; q < 16; q++) {
        int r = tq0 + q;
        float acc = bias;
        acc = fmaf(sxz[(r + 0) * CCD + c], w4.x, acc);
        acc = fmaf(sxz[(r + 1) * CCD + c], w4.y, acc);
        acc = fmaf(sxz[(r + 2) * CCD + c], w4.z, acc);
        acc = fmaf(sxz[(r + 3) * CCD + c], w4.w, acc);
        float o = acc / (1.f + __expf(-acc));
        xa[(size_t)(b * SEQ + t0 + r) * INNER + d0 + c] = o;
    }
}

// ======================= mean finalize (16 partials per token) ===============
__global__ void meanfin_k(const float* __restrict__ part, float* __restrict__ m) {
    int t = blockIdx.x * 256 + threadIdx.x;
    float s = 0.f;
    #pragma unroll
    for (int j = 0; j < 16; j++)
        s += part[(size_t)j * TOK + t];
    m[t] = s * (1.f / (float)INNER);
}

// ======================= segmented parallel scan + gating ====================
#define SEGS   16
#define SEGLEN 64

__device__ __forceinline__ void pow_ladder(float e1, float* p) {
    float e2 = e1 * e1, e4 = e2 * e2, e8 = e4 * e4;
    p[0] = e1;       p[1] = e2;       p[2] = e2 * e1;  p[3] = e4;
    p[4] = e4 * e1;  p[5] = e4 * e2;  p[6] = e4 * p[2]; p[7] = e8;
    p[8] = e8 * e1;  p[9] = e8 * e2;  p[10] = e8 * p[2]; p[11] = e8 * e4;
    p[12] = e8 * p[4]; p[13] = e8 * p[5]; p[14] = e8 * p[6]; p[15] = e8 * e8;
}

__global__ void __launch_bounds__(512)
scan_k(const float* __restrict__ dt,
       const float* __restrict__ xa,
       const float* __restrict__ dtmean,
       const float* __restrict__ bcdtr,
       const float* __restrict__ xz,
       __half* __restrict__ Ao) {
    __shared__ float shH[SEGS][32][NST];
    __shared__ float shS[SEGS][32];

    const int tid = threadIdx.x;
    const int dlane = tid & 31, s = tid >> 5;
    const int b = blockIdx.y;
    const int d = blockIdx.x * 32 + dlane;
    const int t0 = b * SEQ + s * SEGLEN;

    float h[NST];
    #pragma unroll
    for (int n = 0; n < NST; n++) h[n] = 0.f;
    float sdt = 0.f;

    #pragma unroll 2
    for (int i = 0; i < SEGLEN; i++) {
        const int t = t0 + i;
        float dtv = dt[(size_t)t * INNER + d];
        float xav = xa[(size_t)t * INNER + d];
        float dm  = dtmean[t];
        float bx  = dm * xav;
        sdt += dtv;
        float p[NST];
        pow_ladder(__expf(-dtv), p);
        const float4* bp = (const float4*)(bcdtr + (size_t)t * 96);
        float4 b0 = bp[0], b1 = bp[1], b2 = bp[2], b3 = bp[3];
        float Bm[NST] = {b0.x, b0.y, b0.z, b0.w, b1.x, b1.y, b1.z, b1.w,
                         b2.x, b2.y, b2.z, b2.w, b3.x, b3.y, b3.z, b3.w};
        #pragma unroll
        for (int n = 0; n < NST; n++)
            h[n] = fmaf(p[n], h[n], bx * Bm[n]);
    }
    shS[s][dlane] = sdt;
    #pragma unroll
    for (int n = 0; n < NST; n++) shH[s][dlane][n] = h[n];
    __syncthreads();

    float hin[NST];
    #pragma unroll
    for (int n = 0; n < NST; n++) hin[n] = 0.f;
    for (int j = 0; j < s; j++) {
        float p[NST];
        pow_ladder(__expf(-shS[j][dlane]), p);
        #pragma unroll
        for (int n = 0; n < NST; n++)
            hin[n] = fmaf(p[n], hin[n], shH[j][dlane][n]);
    }

    #pragma unroll
    for (int n = 0; n < NST; n++) h[n] = hin[n];

    #pragma unroll 2
    for (int i = 0; i < SEGLEN; i++) {
        const int t = t0 + i;
        float dtv = dt[(size_t)t * INNER + d];
        float xav = xa[(size_t)t * INNER + d];
        float zv  = xz[(size_t)t * (2 * INNER) + INNER + d];
        float dm  = dtmean[t];
        float bx  = dm * xav;
        float p[NST];
        pow_ladder(__expf(-dtv), p);
        const float4* bp = (const float4*)(bcdtr + (size_t)t * 96);
        float4 b0 = bp[0], b1 = bp[1], b2 = bp[2], b3 = bp[3];
        float4 c0 = bp[4], c1 = bp[5], c2 = bp[6], c3 = bp[7];
        float Bm[NST] = {b0.x, b0.y, b0.z, b0.w, b1.x, b1.y, b1.z, b1.w,
                         b2.x, b2.y, b2.z, b2.w, b3.x, b3.y, b3.z, b3.w};
        float Cm[NST] = {c0.x, c0.y, c0.z, c0.w, c1.x, c1.y, c1.z, c1.w,
                         c2.x, c2.y, c2.z, c2.w, c3.x, c3.y, c3.z, c3.w};
        float y0 = 0.f, y1 = 0.f, y2 = 0.f, y3 = 0.f;
        #pragma unroll
        for (int n = 0; n < NST; n += 4) {
            h[n + 0] = fmaf(p[n + 0], h[n + 0], bx * Bm[n + 0]);
            h[n + 1] = fmaf(p[n + 1], h[n + 1], bx * Bm[n + 1]);
            h[n + 2] = fmaf(p[n + 2], h[n + 2], bx * Bm[n + 2]);
            h[n + 3] = fmaf(p[n + 3], h[n + 3], bx * Bm[n + 3]);
            y0 = fmaf(h[n + 0], Cm[n + 0], y0);
            y1 = fmaf(h[n + 1], Cm[n + 1], y1);
            y2 = fmaf(h[n + 2], Cm[n + 2], y2);
            y3 = fmaf(h[n + 3], Cm[n + 3], y3);
        }
        float y = (y0 + y1) + (y2 + y3);
        float sz = zv / (1.f + __expf(-zv));
        Ao[(size_t)t * INNER + d] = __float2half(y * sz);
    }
}

// ======================= launch =============================================
extern "C" void kernel_launch(void* const* d_in, const int* in_sizes, int n_in,
                              void* d_out, int out_size) {
    const float* x      = (const float*)d_in[0];
    const float* norm_w = (const float*)d_in[1];
    const float* norm_b = (const float*)d_in[2];
    const float* in_w   = (const float*)d_in[3];
    const float* in_b   = (const float*)d_in[4];
    const float* conv_w = (const float*)d_in[5];
    const float* conv_b = (const float*)d_in[6];
    const float* bc_w   = (const float*)d_in[7];
    const float* bc_b   = (const float*)d_in[8];
    const float* dtr_w  = (const float*)d_in[9];
    const float* dtr_b  = (const float*)d_in[10];
    const float* dt_w   = (const float*)d_in[11];
    const float* dt_b   = (const float*)d_in[12];
    const float* out_w  = (const float*)d_in[13];
    const float* out_b  = (const float*)d_in[14];
    float* out = (float*)d_out;

    __half *pA_in, *pB_in, *pA_dtr, *pB_dt, *pA_out, *pB_out;
    float *pxz, *pxa, *pbcpart, *pbcdtr, *pdt, *pdtpart, *pdtm;
    cudaGetSymbolAddress((void**)&pA_in,   gA_in);
    cudaGetSymbolAddress((void**)&pB_in,   gB_in);
    cudaGetSymbolAddress((void**)&pxz,     g_xz);
    cudaGetSymbolAddress((void**)&pxa,     g_xa);
    cudaGetSymbolAddress((void**)&pbcpart, g_bcpart);
    cudaGetSymbolAddress((void**)&pbcdtr,  g_bcdtr);
    cudaGetSymbolAddress((void**)&pA_dtr,  gA_dtr);
    cudaGetSymbolAddress((void**)&pB_dt,   gB_dt);
    cudaGetSymbolAddress((void**)&pdt,     g_dt);
    cudaGetSymbolAddress((void**)&pdtpart, g_dtpart);
    cudaGetSymbolAddress((void**)&pdtm,    g_dtmean);
    cudaGetSymbolAddress((void**)&pA_out,  gA_out);
    cudaGetSymbolAddress((void**)&pB_out,  gB_out);

    const int DSMEM  = NSTG * STGB;    // 110592
    const int DSMEMN = NSTG * NSTGB;   // 82944
    cudaFuncSetAttribute(gemm_h<0>, cudaFuncAttributeMaxDynamicSharedMemorySize, DSMEM);
    cudaFuncSetAttribute(gemm_h<1>, cudaFuncAttributeMaxDynamicSharedMemorySize, DSMEM);
    cudaFuncSetAttribute(gemm_n64, cudaFuncAttributeMaxDynamicSharedMemorySize, DSMEMN);

    // 1. LayerNorm -> fp16 A (warp per row)
    layernorm_h_k<<<TOK / 8, 256>>>(x, norm_w, norm_b, pA_in);
    // 2-3. weight conversions (tiled transpose)
    wconv_k<<<dim3((2 * INNER) / 64, H / 64), 256>>>(in_w, pB_in, 2 * INNER, H);
    wconv_k<<<dim3(INNER / 64, DTR / 64), 256>>>(dt_w, pB_dt, INNER, DTR);
    // 4. in-proj GEMM (M=2048, N=4096, K=1024)  <-- ncu capture slot
    gemm_h<0><<<dim3(4096 / 128, TOK / 128), 256, DSMEM>>>(
        pA_in, pB_in, in_b, pxz, nullptr, H, 2 * INNER, 2 * INNER);
    // 5. conv + SiLU (time-tiled smem, 64 tokens) -> xa fp32
    conv_silu_k<<<dim3(INNER / CCD, SEQ / CCT, BATCH), 256>>>(pxz, conv_w, conv_b, pxa);
    // 6a. fp32 bc + dtr projection, split-K x4
    bcproj_k<<<dim3(TOK / 16, 4), 256>>>(pxa, bc_w, dtr_w, pbcpart);
    // 6b. combine partials + bias, emit fp16 dtr
    bccomb_k<<<TOK * 96 / 256, 256>>>(pbcpart, bc_b, dtr_b, pbcdtr, pA_dtr);
    // 7. dt GEMM (M=2048, N=2048, K=64): softplus+clip + per-CTA row sums
    gemm_h<1><<<dim3(INNER / 128, TOK / 128), 256, DSMEM>>>(
        pA_dtr, pB_dt, dt_b, pdt, pdtpart, DTR, INNER, INNER);
    // 8. mean finalize
    meanfin_k<<<TOK / 256, 256>>>(pdtpart, pdtm);
    // 9. segmented parallel scan + gating -> fp16 A
    scan_k<<<dim3(INNER / 32, BATCH), 512>>>(pdt, pxa, pdtm, pbcdtr, pxz, pA_out);
    // 10. out-proj weight conversion
    wconv_k<<<dim3(H / 64, INNER / 64), 256>>>(out_w, pB_out, H, INNER);
    // 11. out-proj GEMM (M=2048, N=1024, K=2048), 128x64 tiles
    gemm_n64<<<dim3(H / NBN, TOK / BM), 256, DSMEMN>>>(
        pA_out, pB_out, out_b, out, INNER, H);
}

// round 17
// speedup vs baseline: 1.2985x; 1.0140x over previous
#include <cuda_runtime.h>
#include <cuda_fp16.h>
#include <cstdint>
#include <math.h>

#define H      1024
#define INNER  2048
#define NST    16
#define DTR    64
#define BATCH  2
#define SEQ    1024
#define TOK    (BATCH*SEQ)   // 2048

// ======================= PTX helpers (plain sm_103 legal) ====================
__device__ __forceinline__ uint32_t smem_u32(const void* p) {
    uint32_t a;
    asm("{ .reg .u64 t; cvta.to.shared.u64 t, %1; cvt.u32.u64 %0, t; }"
        : "=r"(a) : "l"(p));
    return a;
}
__device__ __forceinline__ void cp16(uint32_t saddr, const void* g) {
    asm volatile("cp.async.cg.shared.global [%0], [%1], 16;"
                 :: "r"(saddr), "l"(g) : "memory");
}
#define CP_COMMIT() asm volatile("cp.async.commit_group;" ::: "memory")
#define CP_WAIT1()  asm volatile("cp.async.wait_group 1;" ::: "memory")

__device__ __forceinline__ void ldsm_x4(uint32_t* r, uint32_t addr) {
    asm volatile("ldmatrix.sync.aligned.m8n8.x4.shared.b16 {%0,%1,%2,%3}, [%4];"
                 : "=r"(r[0]), "=r"(r[1]), "=r"(r[2]), "=r"(r[3]) : "r"(addr));
}
__device__ __forceinline__ void mma_f16(float* c, const uint32_t* a, const uint32_t* b) {
    asm volatile("mma.sync.aligned.m16n8k16.row.col.f32.f16.f16.f32 "
                 "{%0,%1,%2,%3}, {%4,%5,%6,%7}, {%8,%9}, {%0,%1,%2,%3};"
                 : "+f"(c[0]), "+f"(c[1]), "+f"(c[2]), "+f"(c[3])
                 : "r"(a[0]), "r"(a[1]), "r"(a[2]), "r"(a[3]),
                   "r"(b[0]), "r"(b[1]));
}

// ======================= scratch buffers ====================================
__device__ __align__(16) __half gA_in [TOK * H];
__device__ __align__(16) __half gB_in [2 * INNER * H];
__device__ __align__(16) float  g_xz  [TOK * 2 * INNER];
__device__ __align__(16) float  g_xa  [TOK * INNER];
__device__ __align__(16) float  g_bcpart[8 * TOK * 96];   // split-K partials
__device__ __align__(16) float  g_bcdtr[TOK * 96];
__device__ __align__(16) __half gA_dtr[TOK * DTR];
__device__ __align__(16) __half gB_dt [INNER * DTR];
__device__ __align__(16) float  g_dt  [TOK * INNER];
__device__ __align__(16) float  g_dtpart[16 * TOK];
__device__                float g_dtmean[TOK];
__device__ __align__(16) __half gA_out[TOK * INNER];
__device__ __align__(16) __half gB_out[H * INNER];

#define LDSTR 72

// ======================= 128x128 warp-MMA GEMM (3-stage) =====================
#define BM    128
#define BN    128
#define BKE   64
#define BUFE  ((BM + BN) * LDSTR)
#define STGB  (BUFE * 2)             // 36864 B
#define NSTG  3

template <int EPI>
__global__ void __launch_bounds__(256, 2)
gemm_h(const __half* __restrict__ A, const __half* __restrict__ B,
       const float* __restrict__ bias, float* __restrict__ C,
       float* __restrict__ part,
       int K, int ldc, int nvalid) {
    extern __shared__ __align__(16) __half sm[];
    const uint32_t smb = smem_u32(sm);

    const int tid = threadIdx.x;
    const int lane = tid & 31, wid = tid >> 5;
    const int m0 = blockIdx.y * BM, n0 = blockIdx.x * BN;
    const int wm = (wid & 3) * 32;
    const int wn = (wid >> 2) * 64;

    float acc[2][8][4];
    #pragma unroll
    for (int i = 0; i < 2; i++)
        #pragma unroll
        for (int j = 0; j < 8; j++)
            #pragma unroll
            for (int k = 0; k < 4; k++) acc[i][j][k] = 0.f;

    const int nc = K >> 6;

    auto load_tile = [&](int stg, int kc) {
        const __half* Ag = A + (size_t)m0 * K + kc * BKE;
        const __half* Bg = B + (size_t)n0 * K + kc * BKE;
        uint32_t sa = smb + stg * STGB;
        uint32_t sbb = sa + BM * LDSTR * 2;
        #pragma unroll
        for (int i = 0; i < 4; i++) {
            int ci = tid + i * 256;
            int row = ci >> 3, c8 = ci & 7;
            uint32_t so = (uint32_t)(row * LDSTR + c8 * 8) * 2;
            cp16(sa + so,  Ag + (size_t)row * K + c8 * 8);
            cp16(sbb + so, Bg + (size_t)row * K + c8 * 8);
        }
    };

    load_tile(0, 0);
    CP_COMMIT();
    if (nc > 1) load_tile(1, 1);
    CP_COMMIT();

    int cs = 0, ls = 2;
    for (int c = 0; c < nc; c++) {
        CP_WAIT1();
        __syncthreads();
        if (c + 2 < nc) {
            load_tile(ls, c + 2);
            ls = (ls + 1 == NSTG) ? 0 : ls + 1;
        }
        CP_COMMIT();

        const uint32_t a_base = smb + cs * STGB;
        const uint32_t b_base = a_base + BM * LDSTR * 2;

        #pragma unroll
        for (int kk = 0; kk < 4; kk++) {
            uint32_t afr[2][4];
            #pragma unroll
            for (int mt = 0; mt < 2; mt++) {
                int row = wm + mt * 16 + (lane & 15);
                int col = kk * 16 + (lane >> 4) * 8;
                ldsm_x4(afr[mt], a_base + (uint32_t)(row * LDSTR + col) * 2);
            }
            uint32_t bfr[8][2];
            #pragma unroll
            for (int p = 0; p < 4; p++) {
                int g = lane >> 3, idx = lane & 7;
                int row = wn + p * 16 + idx + (g >> 1) * 8;
                int col = kk * 16 + (g & 1) * 8;
                uint32_t r[4];
                ldsm_x4(r, b_base + (uint32_t)(row * LDSTR + col) * 2);
                bfr[2 * p][0] = r[0];     bfr[2 * p][1] = r[1];
                bfr[2 * p + 1][0] = r[2]; bfr[2 * p + 1][1] = r[3];
            }
            #pragma unroll
            for (int mt = 0; mt < 2; mt++)
                #pragma unroll
                for (int nt = 0; nt < 8; nt++)
                    mma_f16(acc[mt][nt], afr[mt], bfr[nt]);
        }
        cs = (cs + 1 == NSTG) ? 0 : cs + 1;
    }

    float rs[2][2] = {{0.f, 0.f}, {0.f, 0.f}};

    #pragma unroll
    for (int mt = 0; mt < 2; mt++) {
        #pragma unroll
        for (int nt = 0; nt < 8; nt++) {
            int row = m0 + wm + mt * 16 + (lane >> 2);
            int col = n0 + wn + nt * 8 + (lane & 3) * 2;
            if (col < nvalid) {
                float b0 = bias[col], b1 = bias[col + 1];
                float v00 = acc[mt][nt][0] + b0, v01 = acc[mt][nt][1] + b1;
                float v10 = acc[mt][nt][2] + b0, v11 = acc[mt][nt][3] + b1;
                if (EPI == 1) {
                    v00 = (v00 > 20.f) ? v00 : log1pf(__expf(v00));
                    v01 = (v01 > 20.f) ? v01 : log1pf(__expf(v01));
                    v10 = (v10 > 20.f) ? v10 : log1pf(__expf(v10));
                    v11 = (v11 > 20.f) ? v11 : log1pf(__expf(v11));
                    v00 = fminf(fmaxf(v00, 0.001f), 0.1f);
                    v01 = fminf(fmaxf(v01, 0.001f), 0.1f);
                    v10 = fminf(fmaxf(v10, 0.001f), 0.1f);
                    v11 = fminf(fmaxf(v11, 0.001f), 0.1f);
                    rs[mt][0] += v00 + v01;
                    rs[mt][1] += v10 + v11;
                }
                *(float2*)(C + (size_t)row * ldc + col) = make_float2(v00, v01);
                *(float2*)(C + (size_t)(row + 8) * ldc + col) = make_float2(v10, v11);
            }
        }
    }

    if (EPI == 1) {
        #pragma unroll
        for (int mt = 0; mt < 2; mt++)
            #pragma unroll
            for (int hh = 0; hh < 2; hh++) {
                rs[mt][hh] += __shfl_xor_sync(0xffffffffu, rs[mt][hh], 1);
                rs[mt][hh] += __shfl_xor_sync(0xffffffffu, rs[mt][hh], 2);
            }
        __syncthreads();
        float* sred = (float*)sm;
        if ((lane & 3) == 0) {
            int rb = wm + (lane >> 2);
            int g = (wid >> 2) * 128;
            sred[g + rb]      = rs[0][0];
            sred[g + rb + 8]  = rs[0][1];
            sred[g + rb + 16] = rs[1][0];
            sred[g + rb + 24] = rs[1][1];
        }
        __syncthreads();
        if (tid < 128)
            part[(size_t)blockIdx.x * TOK + m0 + tid] = sred[tid] + sred[128 + tid];
    }
}

// ======================= 128x64 warp-MMA GEMM (3-stage) ======================
#define NBN    64
#define NBUFE  ((BM + NBN) * LDSTR)
#define NSTGB  (NBUFE * 2)            // 27648 B

__global__ void __launch_bounds__(256, 2)
gemm_n64(const __half* __restrict__ A, const __half* __restrict__ B,
         const float* __restrict__ bias, float* __restrict__ C,
         int K, int ldc) {
    extern __shared__ __align__(16) __half sm[];
    const uint32_t smb = smem_u32(sm);

    const int tid = threadIdx.x;
    const int lane = tid & 31, wid = tid >> 5;
    const int m0 = blockIdx.y * BM, n0 = blockIdx.x * NBN;
    const int wm = (wid & 3) * 32;
    const int wn = (wid >> 2) * 32;

    float acc[2][4][4];
    #pragma unroll
    for (int i = 0; i < 2; i++)
        #pragma unroll
        for (int j = 0; j < 4; j++)
            #pragma unroll
            for (int k = 0; k < 4; k++) acc[i][j][k] = 0.f;

    const int nc = K >> 6;

    auto load_tile = [&](int stg, int kc) {
        const __half* Ag = A + (size_t)m0 * K + kc * BKE;
        const __half* Bg = B + (size_t)n0 * K + kc * BKE;
        uint32_t sa = smb + stg * NSTGB;
        uint32_t sbb = sa + BM * LDSTR * 2;
        #pragma unroll
        for (int i = 0; i < 4; i++) {
            int ci = tid + i * 256;
            int row = ci >> 3, c8 = ci & 7;
            uint32_t so = (uint32_t)(row * LDSTR + c8 * 8) * 2;
            cp16(sa + so, Ag + (size_t)row * K + c8 * 8);
        }
        #pragma unroll
        for (int i = 0; i < 2; i++) {
            int ci = tid + i * 256;
            int row = ci >> 3, c8 = ci & 7;
            uint32_t so = (uint32_t)(row * LDSTR + c8 * 8) * 2;
            cp16(sbb + so, Bg + (size_t)row * K + c8 * 8);
        }
    };

    load_tile(0, 0);
    CP_COMMIT();
    if (nc > 1) load_tile(1, 1);
    CP_COMMIT();

    int cs = 0, ls = 2;
    for (int c = 0; c < nc; c++) {
        CP_WAIT1();
        __syncthreads();
        if (c + 2 < nc) {
            load_tile(ls, c + 2);
            ls = (ls + 1 == NSTG) ? 0 : ls + 1;
        }
        CP_COMMIT();

        const uint32_t a_base = smb + cs * NSTGB;
        const uint32_t b_base = a_base + BM * LDSTR * 2;

        #pragma unroll
        for (int kk = 0; kk < 4; kk++) {
            uint32_t afr[2][4];
            #pragma unroll
            for (int mt = 0; mt < 2; mt++) {
                int row = wm + mt * 16 + (lane & 15);
                int col = kk * 16 + (lane >> 4) * 8;
                ldsm_x4(afr[mt], a_base + (uint32_t)(row * LDSTR + col) * 2);
            }
            uint32_t bfr[4][2];
            #pragma unroll
            for (int p = 0; p < 2; p++) {
                int g = lane >> 3, idx = lane & 7;
                int row = wn + p * 16 + idx + (g >> 1) * 8;
                int col = kk * 16 + (g & 1) * 8;
                uint32_t r[4];
                ldsm_x4(r, b_base + (uint32_t)(row * LDSTR + col) * 2);
                bfr[2 * p][0] = r[0];     bfr[2 * p][1] = r[1];
                bfr[2 * p + 1][0] = r[2]; bfr[2 * p + 1][1] = r[3];
            }
            #pragma unroll
            for (int mt = 0; mt < 2; mt++)
                #pragma unroll
                for (int nt = 0; nt < 4; nt++)
                    mma_f16(acc[mt][nt], afr[mt], bfr[nt]);
        }
        cs = (cs + 1 == NSTG) ? 0 : cs + 1;
    }

    #pragma unroll
    for (int mt = 0; mt < 2; mt++) {
        #pragma unroll
        for (int nt = 0; nt < 4; nt++) {
            int row = m0 + wm + mt * 16 + (lane >> 2);
            int col = n0 + wn + nt * 8 + (lane & 3) * 2;
            float b0 = bias[col], b1 = bias[col + 1];
            *(float2*)(C + (size_t)row * ldc + col) =
                make_float2(acc[mt][nt][0] + b0, acc[mt][nt][1] + b1);
            *(float2*)(C + (size_t)(row + 8) * ldc + col) =
                make_float2(acc[mt][nt][2] + b0, acc[mt][nt][3] + b1);
        }
    }
}

// ======================= weight conversion, smem tile transpose ==============
__global__ void __launch_bounds__(256)
wconv_k(const float* __restrict__ W, __half* __restrict__ Bo, int N, int K) {
    __shared__ __half st[64][66];
    const int tid = threadIdx.x;
    const int n0 = blockIdx.x * 64;
    const int k0 = blockIdx.y * 64;

    #pragma unroll 4
    for (int idx = tid; idx < 64 * 64; idx += 256) {
        int kk = idx >> 6, nn = idx & 63;
        st[nn][kk] = __float2half(W[(size_t)(k0 + kk) * N + n0 + nn]);
    }
    __syncthreads();
    #pragma unroll 4
    for (int idx = tid; idx < 64 * 64; idx += 256) {
        int nn = idx >> 6, kk = idx & 63;
        Bo[(size_t)(n0 + nn) * K + k0 + kk] = st[nn][kk];
    }
}

// ======================= fp32 bc+dtr projection, split-K x8 ==================
// grid (TOK/16, 8 k-slices). Each block: 16 tokens x 96 cols over K/8 = 256.
__global__ void __launch_bounds__(256)
bcproj_k(const float* __restrict__ xa,
         const float* __restrict__ bcw, const float* __restrict__ dtw,
         float* __restrict__ part) {
    __shared__ float sW[64][100];
    __shared__ float sA[16][65];
    const int tid = threadIdx.x;
    const int r = tid >> 4, jg = tid & 15;
    const int m0 = blockIdx.x * 16;
    const int ks = blockIdx.y;
    const int kbeg = ks * (INNER / 8);

    float acc[6];
    #pragma unroll
    for (int c = 0; c < 6; c++) acc[c] = 0.f;

    for (int k0 = kbeg; k0 < kbeg + INNER / 8; k0 += 64) {
        __syncthreads();
        for (int idx = tid; idx < 64 * 96; idx += 256) {
            int kl = idx / 96, j = idx % 96;
            float v = (j < 32) ? bcw[(size_t)(k0 + kl) * 32 + j]
                               : dtw[(size_t)(k0 + kl) * 64 + (j - 32)];
            sW[kl][j] = v;
        }
        for (int idx = tid; idx < 16 * 64; idx += 256) {
            int rr = idx >> 6, kl = idx & 63;
            sA[rr][kl] = xa[(size_t)(m0 + rr) * INNER + k0 + kl];
        }
        __syncthreads();
        #pragma unroll 8
        for (int kl = 0; kl < 64; kl++) {
            float a = sA[r][kl];
            const float* wrow = &sW[kl][jg * 6];
            float2 w01 = *(const float2*)(wrow);
            float2 w23 = *(const float2*)(wrow + 2);
            float2 w45 = *(const float2*)(wrow + 4);
            acc[0] = fmaf(a, w01.x, acc[0]);
            acc[1] = fmaf(a, w01.y, acc[1]);
            acc[2] = fmaf(a, w23.x, acc[2]);
            acc[3] = fmaf(a, w23.y, acc[3]);
            acc[4] = fmaf(a, w45.x, acc[4]);
            acc[5] = fmaf(a, w45.y, acc[5]);
        }
    }
    #pragma unroll
    for (int c = 0; c < 6; c++) {
        int j = jg * 6 + c;
        part[((size_t)ks * TOK + m0 + r) * 96 + j] = acc[c];
    }
}

// combine 8 k-slice partials + bias; emit bcdtr fp32 and dtr fp16
__global__ void __launch_bounds__(256)
bccomb_k(const float* __restrict__ part,
         const float* __restrict__ bcb, const float* __restrict__ dtrb,
         float* __restrict__ outp, __half* __restrict__ dtr16) {
    int idx = blockIdx.x * 256 + threadIdx.x;   // over TOK*96
    int t = idx / 96, j = idx - t * 96;
    float s = 0.f;
    #pragma unroll
    for (int k = 0; k < 8; k++)
        s += part[((size_t)k * TOK + t) * 96 + j];
    float bv = (j < 32) ? bcb[j] : dtrb[j - 32];
    float v = s + bv;
    outp[(size_t)t * 96 + j] = v;
    if (j >= 32)
        dtr16[(size_t)t * 64 + (j - 32)] = __float2half(v);
}

// ======================= LayerNorm (warp per row) -> fp16 A ==================
__global__ void __launch_bounds__(256)
layernorm_h_k(const float* __restrict__ x,
              const float* __restrict__ w,
              const float* __restrict__ b,
              __half* __restrict__ Ao) {
    const int lane = threadIdx.x & 31;
    const int row = blockIdx.x * 8 + (threadIdx.x >> 5);
    const float* xr = x + (size_t)row * H;

    float4 v[8];
    float s = 0.f, s2 = 0.f;
    #pragma unroll
    for (int i = 0; i < 8; i++) {
        v[i] = *(const float4*)(xr + (i * 32 + lane) * 4);
        s  += (v[i].x + v[i].y) + (v[i].z + v[i].w);
        s2 += v[i].x * v[i].x + v[i].y * v[i].y + v[i].z * v[i].z + v[i].w * v[i].w;
    }
    #pragma unroll
    for (int o = 16; o > 0; o >>= 1) {
        s  += __shfl_xor_sync(0xffffffffu, s,  o);
        s2 += __shfl_xor_sync(0xffffffffu, s2, o);
    }
    float mu = s / (float)H;
    float rstd = rsqrtf(s2 / (float)H - mu * mu + 1e-5f);

    #pragma unroll
    for (int i = 0; i < 8; i++) {
        int c = (i * 32 + lane) * 4;
        __half2 h0 = __floats2half2_rn((v[i].x - mu) * rstd * w[c]     + b[c],
                                       (v[i].y - mu) * rstd * w[c + 1] + b[c + 1]);
        __half2 h1 = __floats2half2_rn((v[i].z - mu) * rstd * w[c + 2] + b[c + 2],
                                       (v[i].w - mu) * rstd * w[c + 3] + b[c + 3]);
        *(__half2*)(Ao + (size_t)row * H + c)     = h0;
        *(__half2*)(Ao + (size_t)row * H + c + 2) = h1;
    }
}

// ======================= conv(4-tap)+SiLU, time-tiled in smem ================
#define CCT 64
#define CCD 64
__global__ void __launch_bounds__(256)
conv_silu_k(const float* __restrict__ xz,
            const float* __restrict__ cw,
            const float* __restrict__ cb,
            float* __restrict__ xa) {
    __shared__ float sxz[(CCT + 3) * CCD];
    const int tid = threadIdx.x;
    const int d0 = blockIdx.x * CCD;
    const int t0 = blockIdx.y * CCT;
    const int b  = blockIdx.z;

    for (int idx = tid; idx < (CCT + 3) * (CCD / 4); idx += 256) {
        int rr = idx / (CCD / 4);
        int cc = (idx % (CCD / 4)) * 4;
        int tt = t0 - 3 + rr;
        float4 v = make_float4(0.f, 0.f, 0.f, 0.f);
        if (tt >= 0)
            v = *(const float4*)(xz + (size_t)(b * SEQ + tt) * (2 * INNER) + d0 + cc);
        *(float4*)&sxz[rr * CCD + cc] = v;
    }
    __syncthreads();

    const int c = tid & (CCD - 1);
    const int tq0 = (tid >> 6) * 16;
    float4 w4 = *(const float4*)(cw + (d0 + c) * 4);
    float bias = cb[d0 + c];

    #pragma unroll
    for (int q = 0; q < 16; q++) {
        int r = tq0 + q;
        float acc = bias;
        acc = fmaf(sxz[(r + 0) * CCD + c], w4.x, acc);
        acc = fmaf(sxz[(r + 1) * CCD + c], w4.y, acc);
        acc = fmaf(sxz[(r + 2) * CCD + c], w4.z, acc);
        acc = fmaf(sxz[(r + 3) * CCD + c], w4.w, acc);
        float o = acc / (1.f + __expf(-acc));
        xa[(size_t)(b * SEQ + t0 + r) * INNER + d0 + c] = o;
    }
}

// ======================= mean finalize (16 partials per token) ===============
__global__ void meanfin_k(const float* __restrict__ part, float* __restrict__ m) {
    int t = blockIdx.x * 256 + threadIdx.x;
    float s = 0.f;
    #pragma unroll
    for (int j = 0; j < 16; j++)
        s += part[(size_t)j * TOK + t];
    m[t] = s * (1.f / (float)INNER);
}

// ======================= segmented parallel scan + gating ====================
#define SEGS   16
#define SEGLEN 64

__device__ __forceinline__ void pow_ladder(float e1, float* p) {
    float e2 = e1 * e1, e4 = e2 * e2, e8 = e4 * e4;
    p[0] = e1;       p[1] = e2;       p[2] = e2 * e1;  p[3] = e4;
    p[4] = e4 * e1;  p[5] = e4 * e2;  p[6] = e4 * p[2]; p[7] = e8;
    p[8] = e8 * e1;  p[9] = e8 * e2;  p[10] = e8 * p[2]; p[11] = e8 * e4;
    p[12] = e8 * p[4]; p[13] = e8 * p[5]; p[14] = e8 * p[6]; p[15] = e8 * e8;
}

__global__ void __launch_bounds__(512)
scan_k(const float* __restrict__ dt,
       const float* __restrict__ xa,
       const float* __restrict__ dtmean,
       const float* __restrict__ bcdtr,
       const float* __restrict__ xz,
       __half* __restrict__ Ao) {
    __shared__ float shH[SEGS][32][NST];
    __shared__ float shS[SEGS][32];

    const int tid = threadIdx.x;
    const int dlane = tid & 31, s = tid >> 5;
    const int b = blockIdx.y;
    const int d = blockIdx.x * 32 + dlane;
    const int t0 = b * SEQ + s * SEGLEN;

    float h[NST];
    #pragma unroll
    for (int n = 0; n < NST; n++) h[n] = 0.f;
    float sdt = 0.f;

    #pragma unroll 2
    for (int i = 0; i < SEGLEN; i++) {
        const int t = t0 + i;
        float dtv = dt[(size_t)t * INNER + d];
        float xav = xa[(size_t)t * INNER + d];
        float dm  = dtmean[t];
        float bx  = dm * xav;
        sdt += dtv;
        float p[NST];
        pow_ladder(__expf(-dtv), p);
        const float4* bp = (const float4*)(bcdtr + (size_t)t * 96);
        float4 b0 = bp[0], b1 = bp[1], b2 = bp[2], b3 = bp[3];
        float Bm[NST] = {b0.x, b0.y, b0.z, b0.w, b1.x, b1.y, b1.z, b1.w,
                         b2.x, b2.y, b2.z, b2.w, b3.x, b3.y, b3.z, b3.w};
        #pragma unroll
        for (int n = 0; n < NST; n++)
            h[n] = fmaf(p[n], h[n], bx * Bm[n]);
    }
    shS[s][dlane] = sdt;
    #pragma unroll
    for (int n = 0; n < NST; n++) shH[s][dlane][n] = h[n];
    __syncthreads();

    float hin[NST];
    #pragma unroll
    for (int n = 0; n < NST; n++) hin[n] = 0.f;
    for (int j = 0; j < s; j++) {
        float p[NST];
        pow_ladder(__expf(-shS[j][dlane]), p);
        #pragma unroll
        for (int n = 0; n < NST; n++)
            hin[n] = fmaf(p[n], hin[n], shH[j][dlane][n]);
    }

    #pragma unroll
    for (int n = 0; n < NST; n++) h[n] = hin[n];

    #pragma unroll 2
    for (int i = 0; i < SEGLEN; i++) {
        const int t = t0 + i;
        float dtv = dt[(size_t)t * INNER + d];
        float xav = xa[(size_t)t * INNER + d];
        float zv  = xz[(size_t)t * (2 * INNER) + INNER + d];
        float dm  = dtmean[t];
        float bx  = dm * xav;
        float p[NST];
        pow_ladder(__expf(-dtv), p);
        const float4* bp = (const float4*)(bcdtr + (size_t)t * 96);
        float4 b0 = bp[0], b1 = bp[1], b2 = bp[2], b3 = bp[3];
        float4 c0 = bp[4], c1 = bp[5], c2 = bp[6], c3 = bp[7];
        float Bm[NST] = {b0.x, b0.y, b0.z, b0.w, b1.x, b1.y, b1.z, b1.w,
                         b2.x, b2.y, b2.z, b2.w, b3.x, b3.y, b3.z, b3.w};
        float Cm[NST] = {c0.x, c0.y, c0.z, c0.w, c1.x, c1.y, c1.z, c1.w,
                         c2.x, c2.y, c2.z, c2.w, c3.x, c3.y, c3.z, c3.w};
        float y0 = 0.f, y1 = 0.f, y2 = 0.f, y3 = 0.f;
        #pragma unroll
        for (int n = 0; n < NST; n += 4) {
            h[n + 0] = fmaf(p[n + 0], h[n + 0], bx * Bm[n + 0]);
            h[n + 1] = fmaf(p[n + 1], h[n + 1], bx * Bm[n + 1]);
            h[n + 2] = fmaf(p[n + 2], h[n + 2], bx * Bm[n + 2]);
            h[n + 3] = fmaf(p[n + 3], h[n + 3], bx * Bm[n + 3]);
            y0 = fmaf(h[n + 0], Cm[n + 0], y0);
            y1 = fmaf(h[n + 1], Cm[n + 1], y1);
            y2 = fmaf(h[n + 2], Cm[n + 2], y2);
            y3 = fmaf(h[n + 3], Cm[n + 3], y3);
        }
        float y = (y0 + y1) + (y2 + y3);
        float sz = zv / (1.f + __expf(-zv));
        Ao[(size_t)t * INNER + d] = __float2half(y * sz);
    }
}

// ======================= launch =============================================
extern "C" void kernel_launch(void* const* d_in, const int* in_sizes, int n_in,
                              void* d_out, int out_size) {
    const float* x      = (const float*)d_in[0];
    const float* norm_w = (const float*)d_in[1];
    const float* norm_b = (const float*)d_in[2];
    const float* in_w   = (const float*)d_in[3];
    const float* in_b   = (const float*)d_in[4];
    const float* conv_w = (const float*)d_in[5];
    const float* conv_b = (const float*)d_in[6];
    const float* bc_w   = (const float*)d_in[7];
    const float* bc_b   = (const float*)d_in[8];
    const float* dtr_w  = (const float*)d_in[9];
    const float* dtr_b  = (const float*)d_in[10];
    const float* dt_w   = (const float*)d_in[11];
    const float* dt_b   = (const float*)d_in[12];
    const float* out_w  = (const float*)d_in[13];
    const float* out_b  = (const float*)d_in[14];
    float* out = (float*)d_out;

    __half *pA_in, *pB_in, *pA_dtr, *pB_dt, *pA_out, *pB_out;
    float *pxz, *pxa, *pbcpart, *pbcdtr, *pdt, *pdtpart, *pdtm;
    cudaGetSymbolAddress((void**)&pA_in,   gA_in);
    cudaGetSymbolAddress((void**)&pB_in,   gB_in);
    cudaGetSymbolAddress((void**)&pxz,     g_xz);
    cudaGetSymbolAddress((void**)&pxa,     g_xa);
    cudaGetSymbolAddress((void**)&pbcpart, g_bcpart);
    cudaGetSymbolAddress((void**)&pbcdtr,  g_bcdtr);
    cudaGetSymbolAddress((void**)&pA_dtr,  gA_dtr);
    cudaGetSymbolAddress((void**)&pB_dt,   gB_dt);
    cudaGetSymbolAddress((void**)&pdt,     g_dt);
    cudaGetSymbolAddress((void**)&pdtpart, g_dtpart);
    cudaGetSymbolAddress((void**)&pdtm,    g_dtmean);
    cudaGetSymbolAddress((void**)&pA_out,  gA_out);
    cudaGetSymbolAddress((void**)&pB_out,  gB_out);

    const int DSMEM  = NSTG * STGB;    // 110592
    const int DSMEMN = NSTG * NSTGB;   // 82944
    cudaFuncSetAttribute(gemm_h<0>, cudaFuncAttributeMaxDynamicSharedMemorySize, DSMEM);
    cudaFuncSetAttribute(gemm_h<1>, cudaFuncAttributeMaxDynamicSharedMemorySize, DSMEM);
    cudaFuncSetAttribute(gemm_n64, cudaFuncAttributeMaxDynamicSharedMemorySize, DSMEMN);

    // 1. LayerNorm -> fp16 A (warp per row)
    layernorm_h_k<<<TOK / 8, 256>>>(x, norm_w, norm_b, pA_in);
    // 2-3. weight conversions (tiled transpose)
    wconv_k<<<dim3((2 * INNER) / 64, H / 64), 256>>>(in_w, pB_in, 2 * INNER, H);
    wconv_k<<<dim3(INNER / 64, DTR / 64), 256>>>(dt_w, pB_dt, INNER, DTR);
    // 4. in-proj GEMM (M=2048, N=4096, K=1024)  <-- ncu capture slot
    gemm_h<0><<<dim3(4096 / 128, TOK / 128), 256, DSMEM>>>(
        pA_in, pB_in, in_b, pxz, nullptr, H, 2 * INNER, 2 * INNER);
    // 5. conv + SiLU (time-tiled smem) -> xa fp32
    conv_silu_k<<<dim3(INNER / CCD, SEQ / CCT, BATCH), 256>>>(pxz, conv_w, conv_b, pxa);
    // 6a. fp32 bc + dtr projection, split-K x8
    bcproj_k<<<dim3(TOK / 16, 8), 256>>>(pxa, bc_w, dtr_w, pbcpart);
    // 6b. combine partials + bias, emit fp16 dtr
    bccomb_k<<<TOK * 96 / 256, 256>>>(pbcpart, bc_b, dtr_b, pbcdtr, pA_dtr);
    // 7. dt GEMM (M=2048, N=2048, K=64): softplus+clip + per-CTA row sums
    gemm_h<1><<<dim3(INNER / 128, TOK / 128), 256, DSMEM>>>(
        pA_dtr, pB_dt, dt_b, pdt, pdtpart, DTR, INNER, INNER);
    // 8. mean finalize
    meanfin_k<<<TOK / 256, 256>>>(pdtpart, pdtm);
    // 9. segmented parallel scan + gating -> fp16 A
    scan_k<<<dim3(INNER / 32, BATCH), 512>>>(pdt, pxa, pdtm, pbcdtr, pxz, pA_out);
    // 10. out-proj weight conversion
    wconv_k<<<dim3(H / 64, INNER / 64), 256>>>(out_w, pB_out, H, INNER);
    // 11. out-proj GEMM (M=2048, N=1024, K=2048), 128x64 tiles
    gemm_n64<<<dim3(H / NBN, TOK / BM), 256, DSMEMN>>>(
        pA_out, pB_out, out_b, out, INNER, H);
}